// round 1
// baseline (speedup 1.0000x reference)
#include <cuda_runtime.h>

// Problem constants (fixed shapes per reference)
#define B_N   4
#define C_N   96
#define H_N   256
#define W_N   256
#define KTOT  288          // 3*C
#define NTHREADS 384
#define YSTRIDE  260       // 256 pixels + 4 pad (keeps 16B alignment)
#define WS_FLOATS (KTOT * C_N)        // 27648
#define YS_FLOATS (C_N * YSTRIDE)     // 24960
#define SMEM_FLOATS (WS_FLOATS + YS_FLOATS)
#define SMEM_BYTES (SMEM_FLOATS * 4)  // 210432

// Transposed weights [k][o], filled once per launch by a tiny kernel.
__device__ float g_Wt[KTOT * C_N];

__global__ void transpose_w_kernel(const float* __restrict__ w) {
    int i = blockIdx.x * 256 + threadIdx.x;
    if (i < C_N * KTOT) {
        int o = i / KTOT;
        int k = i - o * KTOT;
        g_Wt[k * C_N + o] = w[i];
    }
}

__device__ __forceinline__ void fma2(unsigned long long& d, unsigned long long a, unsigned long long b) {
    asm("fma.rn.f32x2 %0, %1, %2, %0;" : "+l"(d) : "l"(a), "l"(b));
}
__device__ __forceinline__ unsigned long long dup2(float x) {
    unsigned long long r;
    asm("mov.b64 %0, {%1, %1};" : "=l"(r) : "f"(x));
    return r;
}
__device__ __forceinline__ float2 unpack2(unsigned long long v) {
    float2 f;
    asm("mov.b64 {%0, %1}, %2;" : "=f"(f.x), "=f"(f.y) : "l"(v));
    return f;
}
__device__ __forceinline__ float ffm_sel(float a, float b) {
    return (fabsf(a) >= fabsf(b)) ? a : b;
}

// Fused: DWT-fuse-IDWT (chunk 0) + copy x2/x3 (chunks 1/2), streamed into a
// register-tiled GEMM  out[96, pix] = Wt[288,96]^T * Y[288, pix].
__global__ void __launch_bounds__(NTHREADS, 1)
fused_dwt_gemm_kernel(const float* __restrict__ x1, const float* __restrict__ x2,
                      const float* __restrict__ x3, float* __restrict__ out) {
    extern __shared__ float smem[];
    float* Ws = smem;               // full Wt copy: [k*96 + o]
    float* Ys = smem + WS_FLOATS;   // Y panel: [c*YSTRIDE + p], p = row*128 + col

    const int tid = threadIdx.x;
    const int bid = blockIdx.x;
    const int b   = bid >> 8;           // 4 batches * 256 blocks each
    const int r   = (bid >> 1) & 127;   // row-pair index (rows 2r, 2r+1)
    const int j0  = (bid & 1) << 7;     // col base 0 or 128

    // ---- stage Wt into smem (coalesced float4) ----
    {
        const float4* src = (const float4*)g_Wt;
        float4* dst = (float4*)Ws;
        #pragma unroll
        for (int i = tid; i < WS_FLOATS / 4; i += NTHREADS) dst[i] = src[i];
    }

    const int lane = tid & 31;
    const int warp = tid >> 5;     // 12 warps -> 12 M-groups of 8
    const int m0   = warp * 8;
    const int p0   = lane * 8;     // 8 pixels per thread (never crosses row boundary)
    const int prow = p0 >> 7;      // 0 or 1 within tile
    const int pcol = p0 & 127;

    unsigned long long acc[4][8];  // [m-pair][pixel] packed f32x2 over (m0+2j, m0+2j+1)
    #pragma unroll
    for (int j = 0; j < 4; ++j)
        #pragma unroll
        for (int p = 0; p < 8; ++p) acc[j][p] = 0ULL;

    const int chs = H_N * W_N;
    const int rowbase = ((b * C_N) * H_N + 2 * r) * W_N + j0;  // + c*chs

    for (int chunk = 0; chunk < 3; ++chunk) {
        if (chunk > 0) __syncthreads();   // previous GEMM done reading Ys

        if (chunk == 0) {
            // x_rec: 96 channels * 64 col-pairs = 6144 units, 16/thread
            #pragma unroll 4
            for (int it = 0; it < 6144 / NTHREADS; ++it) {
                int q = tid + it * NTHREADS;
                int c = q >> 6;
                int u = q & 63;
                int off = rowbase + c * chs + 2 * u;

                float2 t1 = *(const float2*)(x1 + off);
                float2 g1 = *(const float2*)(x1 + off + W_N);
                float2 t2 = *(const float2*)(x2 + off);
                float2 g2 = *(const float2*)(x2 + off + W_N);
                float2 t3 = *(const float2*)(x3 + off);
                float2 g3 = *(const float2*)(x3 + off + W_N);

                // Haar per input: a=even/even, b=odd/even, c=even/odd, d=odd/odd
                float s1, s2, u1, u2;
                s1 = t1.x + g1.x; s2 = t1.y + g1.y; u1 = g1.x - t1.x; u2 = g1.y - t1.y;
                float A1 = 0.5f * (s1 + s2), B1 = 0.5f * (s2 - s1);
                float C1 = 0.5f * (u1 + u2), D1 = 0.5f * (u2 - u1);
                s1 = t2.x + g2.x; s2 = t2.y + g2.y; u1 = g2.x - t2.x; u2 = g2.y - t2.y;
                float A2 = 0.5f * (s1 + s2), B2 = 0.5f * (s2 - s1);
                float C2 = 0.5f * (u1 + u2), D2 = 0.5f * (u2 - u1);
                s1 = t3.x + g3.x; s2 = t3.y + g3.y; u1 = g3.x - t3.x; u2 = g3.y - t3.y;
                float A3 = 0.5f * (s1 + s2), B3 = 0.5f * (s2 - s1);
                float C3 = 0.5f * (u1 + u2), D3 = 0.5f * (u2 - u1);

                float A  = (A1 + A2 + A3) * (1.0f / 3.0f);
                float Bv = ffm_sel(ffm_sel(B1, B2), B3);
                float Cv = ffm_sel(ffm_sel(C1, C2), C3);
                float Dv = ffm_sel(ffm_sel(D1, D2), D3);

                // IDWT (*2 folded): q=0.25 * 2 = 0.5
                float r0c0 = 0.5f * (A - Bv - Cv + Dv);
                float r0c1 = 0.5f * (A + Bv - Cv - Dv);
                float r1c0 = 0.5f * (A - Bv + Cv - Dv);
                float r1c1 = 0.5f * (A + Bv + Cv + Dv);

                float* yr = Ys + c * YSTRIDE;
                *(float2*)(yr + 2 * u)       = make_float2(r0c0, r0c1);
                *(float2*)(yr + 128 + 2 * u) = make_float2(r1c0, r1c1);
            }
        } else {
            const float* xs = (chunk == 1) ? x2 : x3;
            // 96 ch * 2 rows * 32 float4 = 6144 float4, 16/thread
            #pragma unroll 4
            for (int it = 0; it < 6144 / NTHREADS; ++it) {
                int q = tid + it * NTHREADS;
                int c  = q >> 6;
                int rr = (q >> 5) & 1;
                int c4 = q & 31;
                int off = rowbase + c * chs + rr * W_N + c4 * 4;
                float4 v = *(const float4*)(xs + off);
                *(float4*)(Ys + c * YSTRIDE + rr * 128 + c4 * 4) = v;
            }
        }
        __syncthreads();

        // ---- register GEMM over this 96-channel chunk ----
        const float* Wc = Ws + chunk * 96 * C_N;
        #pragma unroll 2
        for (int k = 0; k < 96; ++k) {
            const ulonglong2* wv = (const ulonglong2*)(Wc + k * C_N + m0);
            ulonglong2 wA = wv[0];
            ulonglong2 wB = wv[1];
            unsigned long long wp0 = wA.x, wp1 = wA.y, wp2 = wB.x, wp3 = wB.y;

            const float4* yv = (const float4*)(Ys + k * YSTRIDE + p0);
            float4 ya = yv[0], yb = yv[1];
            float ys8[8] = {ya.x, ya.y, ya.z, ya.w, yb.x, yb.y, yb.z, yb.w};

            #pragma unroll
            for (int p = 0; p < 8; ++p) {
                unsigned long long yd = dup2(ys8[p]);
                fma2(acc[0][p], wp0, yd);
                fma2(acc[1][p], wp1, yd);
                fma2(acc[2][p], wp2, yd);
                fma2(acc[3][p], wp3, yd);
            }
        }
    }

    // ---- epilogue: 64 outputs/thread as float4 stores ----
    const int orow = 2 * r + prow;
    #pragma unroll
    for (int j = 0; j < 4; ++j) {
        float lo[8], hi[8];
        #pragma unroll
        for (int p = 0; p < 8; ++p) {
            float2 v = unpack2(acc[j][p]);
            lo[p] = v.x;
            hi[p] = v.y;
        }
        int mlo = m0 + 2 * j;
        float* olo = out + (((b * C_N + mlo) * H_N + orow) * W_N) + j0 + pcol;
        float* ohi = olo + chs;   // next output channel
        *(float4*)(olo)     = make_float4(lo[0], lo[1], lo[2], lo[3]);
        *(float4*)(olo + 4) = make_float4(lo[4], lo[5], lo[6], lo[7]);
        *(float4*)(ohi)     = make_float4(hi[0], hi[1], hi[2], hi[3]);
        *(float4*)(ohi + 4) = make_float4(hi[4], hi[5], hi[6], hi[7]);
    }
}

extern "C" void kernel_launch(void* const* d_in, const int* in_sizes, int n_in,
                              void* d_out, int out_size) {
    // Inputs per metadata order: x1, x2, x3 (25165824 each), w_out (27648).
    // Defensive: locate the small weight tensor by size.
    const float* xs[3];
    const float* w = nullptr;
    int nx = 0;
    for (int i = 0; i < n_in; ++i) {
        if (in_sizes[i] == C_N * KTOT) w = (const float*)d_in[i];
        else if (nx < 3) xs[nx++] = (const float*)d_in[i];
    }
    float* out = (float*)d_out;

    cudaFuncSetAttribute(fused_dwt_gemm_kernel,
                         cudaFuncAttributeMaxDynamicSharedMemorySize, SMEM_BYTES);

    transpose_w_kernel<<<(C_N * KTOT + 255) / 256, 256>>>(w);
    fused_dwt_gemm_kernel<<<B_N * 128 * 2, NTHREADS, SMEM_BYTES>>>(xs[0], xs[1], xs[2], out);
}

// round 3
// speedup vs baseline: 2.0959x; 2.0959x over previous
#include <cuda_runtime.h>
#include <cuda_bf16.h>
#include <stdint.h>

// ---------------- problem constants ----------------
#define B_N 4
#define C_N 96
#define H_N 256
#define W_N 256
#define CHS (H_N * W_N)
#define NTH 256
#define KSTEPS 18            // 288 / 16
#define KSL 6                // k-steps per 96-channel chunk
#define YSTR 136             // halves per Y row (128 + 8 pad) -> 272B, 16B-aligned

// smem layout (bytes)
#define YROW_B (YSTR * 2)                 // 272
#define YSZ (96 * YROW_B)                 // 26112 per version
#define OFF_YHI 0
#define OFF_YLO YSZ                       // 26112
#define OFF_WF  (2 * YSZ)                 // 52224
#define WFSZ (KSL * 12 * 32 * 16)         // 36864
#define SMEM_SZ (OFF_WF + WFSZ)           // 89088

// W fragments: [kstep 0..17][ntile 0..11][lane 0..31] = uint4 {b0h,b1h,b0l,b1l}
__device__ uint4 g_Wf[KSTEPS * 12 * 32];

// ---------------- helpers ----------------
static __device__ __forceinline__ uint32_t smem_u32(const void* p) {
    uint32_t a;
    asm("{ .reg .u64 t; cvta.to.shared.u64 t, %1; cvt.u32.u64 %0, t; }" : "=r"(a) : "l"(p));
    return a;
}
static __device__ __forceinline__ uint32_t pack_bf16(float a, float b) {
    __nv_bfloat162 h = __floats2bfloat162_rn(a, b);
    return *(uint32_t*)&h;
}
static __device__ __forceinline__ float bf16_hi_f(float v) {
    __nv_bfloat16 h = __float2bfloat16(v);
    return __bfloat162float(h);
}
static __device__ __forceinline__ void ldsm4t(uint32_t* r, uint32_t addr) {
    asm volatile("ldmatrix.sync.aligned.m8n8.x4.trans.shared.b16 {%0,%1,%2,%3}, [%4];"
                 : "=r"(r[0]), "=r"(r[1]), "=r"(r[2]), "=r"(r[3]) : "r"(addr));
}
static __device__ __forceinline__ void mma16816(float* d, const uint32_t* a,
                                                uint32_t b0, uint32_t b1) {
    asm volatile(
        "mma.sync.aligned.m16n8k16.row.col.f32.bf16.bf16.f32 "
        "{%0,%1,%2,%3}, {%4,%5,%6,%7}, {%8,%9}, {%0,%1,%2,%3};"
        : "+f"(d[0]), "+f"(d[1]), "+f"(d[2]), "+f"(d[3])
        : "r"(a[0]), "r"(a[1]), "r"(a[2]), "r"(a[3]), "r"(b0), "r"(b1));
}
static __device__ __forceinline__ float ffm_sel(float a, float b) {
    return (fabsf(a) >= fabsf(b)) ? a : b;
}

// ---------------- prep: W -> per-lane B fragments (hi/lo split) ----------------
__global__ void prep_w_kernel(const float* __restrict__ w) {
    int i = blockIdx.x * 256 + threadIdx.x;
    if (i >= KSTEPS * 12 * 32) return;
    int lane = i & 31;
    int nt = (i >> 5) % 12;
    int ks = i / (12 * 32);
    int o = nt * 8 + (lane >> 2);
    int t = lane & 3;
    int k0 = ks * 16;
    float w0 = w[o * 288 + k0 + 2 * t];
    float w1 = w[o * 288 + k0 + 2 * t + 1];
    float w2 = w[o * 288 + k0 + 2 * t + 8];
    float w3 = w[o * 288 + k0 + 2 * t + 9];
    float h0 = bf16_hi_f(w0), h1 = bf16_hi_f(w1), h2 = bf16_hi_f(w2), h3 = bf16_hi_f(w3);
    uint4 v;
    v.x = pack_bf16(h0, h1);                  // b0 hi
    v.y = pack_bf16(h2, h3);                  // b1 hi
    v.z = pack_bf16(w0 - h0, w1 - h1);        // b0 lo
    v.w = pack_bf16(w2 - h2, w3 - h3);        // b1 lo
    g_Wf[i] = v;
}

// ---------------- fused DWT + concat + 1x1 conv via mma.sync ----------------
// Block: 128 pixels (rows {2r,2r+1} x 64 cols @ j0) x 96 outputs.
// D[pix, out] = sum_k Y[pix, k] * W[out, k]; A = Y (row-major), B = W (col-major).
__global__ void __launch_bounds__(NTH, 2)
fused_mma_kernel(const float* __restrict__ x1, const float* __restrict__ x2,
                 const float* __restrict__ x3, float* __restrict__ out) {
    extern __shared__ unsigned char smem[];
    const uint32_t sb = smem_u32(smem);

    const int tid = threadIdx.x;
    const int wid = tid >> 5;
    const int lane = tid & 31;
    const int bid = blockIdx.x;
    const int b  = bid >> 9;            // 512 blocks per batch
    const int r  = (bid >> 2) & 127;    // row-pair index
    const int j0 = (bid & 3) << 6;      // col base: 0,64,128,192

    const int pg = wid & 3;             // pixel group (32 pixels)
    const int oh = wid >> 2;            // output half (48 outs)
    const int pixb = pg * 32;

    // ldmatrix lane offset (halves), per mtile; +ksl*16*YSTR per k-step
    const int g2 = lane >> 3, jj = lane & 7;
    const int krow = ((g2 & 2) << 2) + jj;      // 0..15
    const int pxo  = (g2 & 1) << 3;             // 0 or 8
    const uint32_t lmoff0 = (uint32_t)(krow * YSTR + pixb + pxo) * 2;
    const uint32_t lmoff1 = lmoff0 + 16 * 2;    // mtile 1: +16 pixels

    float d[2][6][4];
    #pragma unroll
    for (int mt = 0; mt < 2; ++mt)
        #pragma unroll
        for (int nt = 0; nt < 6; ++nt)
            #pragma unroll
            for (int q = 0; q < 4; ++q) d[mt][nt][q] = 0.0f;

    const int rowbase = ((b * C_N) * H_N + 2 * r) * W_N + j0;  // + ch*CHS

    for (int chunk = 0; chunk < 3; ++chunk) {
        // ---- stage W fragment slice (coalesced uint4) ----
        {
            const uint4* src = g_Wf + chunk * (KSL * 12 * 32);
            uint4* dst = (uint4*)(smem + OFF_WF);
            #pragma unroll
            for (int i = tid; i < KSL * 12 * 32; i += NTH) dst[i] = src[i];
        }
        // ---- stage Y chunk: 96 k-rows x 128 pixels, bf16 hi/lo, k-major ----
        if (chunk == 0) {
            // x_rec: DWT -> ffm -> IDWT; item = (k, col-pair u)
            #pragma unroll
            for (int it = 0; it < 96 * 32 / NTH; ++it) {
                int q = tid + it * NTH;
                int k = q >> 5;
                int u = q & 31;
                int off = rowbase + k * CHS + 2 * u;
                float2 t1 = *(const float2*)(x1 + off);
                float2 g1 = *(const float2*)(x1 + off + W_N);
                float2 t2 = *(const float2*)(x2 + off);
                float2 g2v = *(const float2*)(x2 + off + W_N);
                float2 t3 = *(const float2*)(x3 + off);
                float2 g3 = *(const float2*)(x3 + off + W_N);
                float s1, s2, w1, w2;
                s1 = t1.x + g1.x; s2 = t1.y + g1.y; w1 = g1.x - t1.x; w2 = g1.y - t1.y;
                float A1 = 0.5f*(s1+s2), B1 = 0.5f*(s2-s1), C1 = 0.5f*(w1+w2), D1 = 0.5f*(w2-w1);
                s1 = t2.x + g2v.x; s2 = t2.y + g2v.y; w1 = g2v.x - t2.x; w2 = g2v.y - t2.y;
                float A2 = 0.5f*(s1+s2), B2 = 0.5f*(s2-s1), C2 = 0.5f*(w1+w2), D2 = 0.5f*(w2-w1);
                s1 = t3.x + g3.x; s2 = t3.y + g3.y; w1 = g3.x - t3.x; w2 = g3.y - t3.y;
                float A3 = 0.5f*(s1+s2), B3 = 0.5f*(s2-s1), C3 = 0.5f*(w1+w2), D3 = 0.5f*(w2-w1);
                float A  = (A1 + A2 + A3) * (1.0f / 3.0f);
                float Bv = ffm_sel(ffm_sel(B1, B2), B3);
                float Cv = ffm_sel(ffm_sel(C1, C2), C3);
                float Dv = ffm_sel(ffm_sel(D1, D2), D3);
                float v0 = 0.5f * (A - Bv - Cv + Dv);   // even row, even col
                float v1 = 0.5f * (A + Bv - Cv - Dv);   // even row, odd col
                float v2 = 0.5f * (A - Bv + Cv - Dv);   // odd row, even col
                float v3 = 0.5f * (A + Bv + Cv + Dv);   // odd row, odd col
                float h0 = bf16_hi_f(v0), h1 = bf16_hi_f(v1);
                float h2 = bf16_hi_f(v2), h3 = bf16_hi_f(v3);
                uint32_t* yh = (uint32_t*)(smem + OFF_YHI + k * YROW_B);
                uint32_t* yl = (uint32_t*)(smem + OFF_YLO + k * YROW_B);
                yh[u]      = pack_bf16(h0, h1);
                yh[32 + u] = pack_bf16(h2, h3);
                yl[u]      = pack_bf16(v0 - h0, v1 - h1);
                yl[32 + u] = pack_bf16(v2 - h2, v3 - h3);
            }
        } else {
            const float* xs = (chunk == 1) ? x2 : x3;
            #pragma unroll
            for (int it = 0; it < 96 * 32 / NTH; ++it) {
                int q = tid + it * NTH;
                int k = q >> 5;
                int p4 = q & 31;              // group of 4 pixels
                int rr = p4 >> 4, c4 = p4 & 15;
                float4 v = *(const float4*)(xs + rowbase + k * CHS + rr * W_N + c4 * 4);
                float h0 = bf16_hi_f(v.x), h1 = bf16_hi_f(v.y);
                float h2 = bf16_hi_f(v.z), h3 = bf16_hi_f(v.w);
                int pp = (rr * 64 + c4 * 4) >> 1;   // in b32 units
                uint32_t* yh = (uint32_t*)(smem + OFF_YHI + k * YROW_B);
                uint32_t* yl = (uint32_t*)(smem + OFF_YLO + k * YROW_B);
                yh[pp]     = pack_bf16(h0, h1);
                yh[pp + 1] = pack_bf16(h2, h3);
                yl[pp]     = pack_bf16(v.x - h0, v.y - h1);
                yl[pp + 1] = pack_bf16(v.z - h2, v.w - h3);
            }
        }
        __syncthreads();

        // ---- GEMM over this chunk: 6 k-steps of 16 ----
        #pragma unroll
        for (int ksl = 0; ksl < KSL; ++ksl) {
            uint32_t kadd = (uint32_t)(ksl * 16 * YROW_B);
            uint32_t ah[2][4], al[2][4];
            ldsm4t(ah[0], sb + OFF_YHI + kadd + lmoff0);
            ldsm4t(ah[1], sb + OFF_YHI + kadd + lmoff1);
            ldsm4t(al[0], sb + OFF_YLO + kadd + lmoff0);
            ldsm4t(al[1], sb + OFF_YLO + kadd + lmoff1);
            const uint4* wf = (const uint4*)(smem + OFF_WF) + (ksl * 12 + oh * 6) * 32 + lane;
            #pragma unroll
            for (int nt = 0; nt < 6; ++nt) {
                uint4 wv = wf[nt * 32];
                #pragma unroll
                for (int mt = 0; mt < 2; ++mt) {
                    mma16816(d[mt][nt], ah[mt], wv.x, wv.y);  // hi * hi
                    mma16816(d[mt][nt], ah[mt], wv.z, wv.w);  // hi * lo
                    mma16816(d[mt][nt], al[mt], wv.x, wv.y);  // lo * hi
                }
            }
        }
        __syncthreads();
    }

    // ---- epilogue: scattered-but-sectored STG.32 ----
    // d regs: d0=(pix g, out 2t), d1=(g, 2t+1), d2=(g+8, 2t), d3=(g+8, 2t+1)
    {
        const int g = lane >> 2, t = lane & 3;
        const int prow = pg >> 1;
        const int pcolb = (pg & 1) * 32;
        #pragma unroll
        for (int mt = 0; mt < 2; ++mt) {
            float* ob = out + ((size_t)(b * C_N + oh * 48) * H_N + 2 * r + prow) * W_N
                        + j0 + pcolb + mt * 16 + g;
            #pragma unroll
            for (int nt = 0; nt < 6; ++nt) {
                float* oc = ob + (size_t)(nt * 8 + 2 * t) * CHS;
                oc[0]       = d[mt][nt][0];
                oc[CHS]     = d[mt][nt][1];
                oc[8]       = d[mt][nt][2];
                oc[CHS + 8] = d[mt][nt][3];
            }
        }
    }
}

// ---------------- launch ----------------
extern "C" void kernel_launch(void* const* d_in, const int* in_sizes, int n_in,
                              void* d_out, int out_size) {
    const float* xs[3];
    const float* w = nullptr;
    int nx = 0;
    for (int i = 0; i < n_in; ++i) {
        if (in_sizes[i] == C_N * 288) w = (const float*)d_in[i];
        else if (nx < 3) xs[nx++] = (const float*)d_in[i];
    }
    float* out = (float*)d_out;

    cudaFuncSetAttribute(fused_mma_kernel,
                         cudaFuncAttributeMaxDynamicSharedMemorySize, SMEM_SZ);

    prep_w_kernel<<<(KSTEPS * 12 * 32 + 255) / 256, 256>>>(w);
    fused_mma_kernel<<<B_N * 128 * 4, NTH, SMEM_SZ>>>(xs[0], xs[1], xs[2], out);
}

// round 5
// speedup vs baseline: 2.5589x; 1.2209x over previous
#include <cuda_runtime.h>
#include <cuda_fp16.h>
#include <stdint.h>

// ---------------- problem constants ----------------
#define B_N 4
#define C_N 96
#define H_N 256
#define W_N 256
#define CHS (H_N * W_N)
#define NTH 256
#define KSTEPS 18            // 288 / 16
#define KSL 6                // k-steps per 96-channel chunk
#define YSTR 136             // halves per Y row (128 + 8 pad) -> 272B

// smem layout (bytes)
#define YROW_B (YSTR * 2)                 // 272
#define YSZ (96 * YROW_B)                 // 26112 per version
#define OFF_YHI 0
#define OFF_YLO YSZ                       // 26112
#define OFF_W  (2 * YSZ)                  // 52224
#define WSZ (KSTEPS * 6 * 32 * 16)        // 55296 (all k-steps, hi only)
#define SMEM_SZ (OFF_W + WSZ)             // 107520

// W fragments (hi only): [kstep][pair q=0..5][lane] uint4 =
//   {b0(nt=2q), b1(2q), b0(2q+1), b1(2q+1)}
__device__ uint4 g_Wf[KSTEPS * 6 * 32];

// ---------------- helpers ----------------
static __device__ __forceinline__ uint32_t smem_u32(const void* p) {
    uint32_t a;
    asm("{ .reg .u64 t; cvta.to.shared.u64 t, %1; cvt.u32.u64 %0, t; }" : "=r"(a) : "l"(p));
    return a;
}
static __device__ __forceinline__ uint32_t pack_h2(float a, float b) {
    __half2 h = __floats2half2_rn(a, b);
    return *(uint32_t*)&h;
}
static __device__ __forceinline__ float h_hi_f(float v) {
    return __half2float(__float2half_rn(v));
}
static __device__ __forceinline__ void ldsm4t(uint32_t* r, uint32_t addr) {
    asm volatile("ldmatrix.sync.aligned.m8n8.x4.trans.shared.b16 {%0,%1,%2,%3}, [%4];"
                 : "=r"(r[0]), "=r"(r[1]), "=r"(r[2]), "=r"(r[3]) : "r"(addr));
}
static __device__ __forceinline__ void mma16816(float* d, const uint32_t* a,
                                                uint32_t b0, uint32_t b1) {
    asm volatile(
        "mma.sync.aligned.m16n8k16.row.col.f32.f16.f16.f32 "
        "{%0,%1,%2,%3}, {%4,%5,%6,%7}, {%8,%9}, {%0,%1,%2,%3};"
        : "+f"(d[0]), "+f"(d[1]), "+f"(d[2]), "+f"(d[3])
        : "r"(a[0]), "r"(a[1]), "r"(a[2]), "r"(a[3]), "r"(b0), "r"(b1));
}
static __device__ __forceinline__ float ffm_sel(float a, float b) {
    return (fabsf(a) >= fabsf(b)) ? a : b;
}

// ---------------- prep: W -> per-lane fp16 B fragments (hi only) ----------------
__global__ void prep_w_kernel(const float* __restrict__ w) {
    int i = blockIdx.x * 256 + threadIdx.x;
    if (i >= KSTEPS * 6 * 32) return;
    int lane = i & 31;
    int q = (i >> 5) % 6;
    int ks = i / (6 * 32);
    int t = lane & 3;
    int g = lane >> 2;
    int k0 = ks * 16;
    int oe = (2 * q) * 8 + g;
    int oo = (2 * q + 1) * 8 + g;
    uint4 v;
    v.x = pack_h2(w[oe * 288 + k0 + 2 * t],     w[oe * 288 + k0 + 2 * t + 1]);
    v.y = pack_h2(w[oe * 288 + k0 + 2 * t + 8], w[oe * 288 + k0 + 2 * t + 9]);
    v.z = pack_h2(w[oo * 288 + k0 + 2 * t],     w[oo * 288 + k0 + 2 * t + 1]);
    v.w = pack_h2(w[oo * 288 + k0 + 2 * t + 8], w[oo * 288 + k0 + 2 * t + 9]);
    g_Wf[i] = v;
}

// ---------------- fused DWT + concat + 1x1 conv, pipelined mma.sync ----------------
__global__ void __launch_bounds__(NTH, 2)
fused_mma_kernel(const float* __restrict__ x1, const float* __restrict__ x2,
                 const float* __restrict__ x3, float* __restrict__ out) {
    extern __shared__ unsigned char smem[];
    const uint32_t sb = smem_u32(smem);

    const int tid = threadIdx.x;
    const int wid = tid >> 5;
    const int lane = tid & 31;
    const int bid = blockIdx.x;
    const int b  = bid >> 9;
    const int r  = (bid >> 2) & 127;
    const int j0 = (bid & 3) << 6;

    const int pg = wid & 3;             // pixel group (32 pixels)
    const int oh = wid >> 2;            // output half (48 outs)
    const int pixb = pg * 32;

    const int g2 = lane >> 3, jj = lane & 7;
    const int krow = ((g2 & 2) << 2) + jj;
    const int pxo  = (g2 & 1) << 3;
    const uint32_t lmoff0 = (uint32_t)(krow * YSTR + pixb + pxo) * 2;
    const uint32_t lmoff1 = lmoff0 + 32;

    float d[2][6][4];
    #pragma unroll
    for (int mt = 0; mt < 2; ++mt)
        #pragma unroll
        for (int nt = 0; nt < 6; ++nt)
            #pragma unroll
            for (int q = 0; q < 4; ++q) d[mt][nt][q] = 0.0f;

    const int rowbase = ((b * C_N) * H_N + 2 * r) * W_N + j0;

    // ---- stage ALL W fragments once (55296 B) ----
    {
        const uint4* src = g_Wf;
        uint4* dst = (uint4*)(smem + OFF_W);
        #pragma unroll
        for (int i = tid; i < KSTEPS * 6 * 32; i += NTH) dst[i] = src[i];
    }

    // ---- chunk0 staging: DWT -> ffm -> IDWT, item = (k, col-pair u) ----
    {
        #pragma unroll 4
        for (int it = 0; it < 12; ++it) {
            int q = tid + it * NTH;
            int k = q >> 5;
            int u = q & 31;
            int off = rowbase + k * CHS + 2 * u;
            float2 t1 = *(const float2*)(x1 + off);
            float2 g1 = *(const float2*)(x1 + off + W_N);
            float2 t2 = *(const float2*)(x2 + off);
            float2 g2v = *(const float2*)(x2 + off + W_N);
            float2 t3 = *(const float2*)(x3 + off);
            float2 g3 = *(const float2*)(x3 + off + W_N);
            float s1, s2, w1, w2;
            s1 = t1.x + g1.x; s2 = t1.y + g1.y; w1 = g1.x - t1.x; w2 = g1.y - t1.y;
            float A1 = 0.5f*(s1+s2), B1 = 0.5f*(s2-s1), C1 = 0.5f*(w1+w2), D1 = 0.5f*(w2-w1);
            s1 = t2.x + g2v.x; s2 = t2.y + g2v.y; w1 = g2v.x - t2.x; w2 = g2v.y - t2.y;
            float A2 = 0.5f*(s1+s2), B2 = 0.5f*(s2-s1), C2 = 0.5f*(w1+w2), D2 = 0.5f*(w2-w1);
            s1 = t3.x + g3.x; s2 = t3.y + g3.y; w1 = g3.x - t3.x; w2 = g3.y - t3.y;
            float A3 = 0.5f*(s1+s2), B3 = 0.5f*(s2-s1), C3 = 0.5f*(w1+w2), D3 = 0.5f*(w2-w1);
            float A  = (A1 + A2 + A3) * (1.0f / 3.0f);
            float Bv = ffm_sel(ffm_sel(B1, B2), B3);
            float Cv = ffm_sel(ffm_sel(C1, C2), C3);
            float Dv = ffm_sel(ffm_sel(D1, D2), D3);
            float v0 = 0.5f * (A - Bv - Cv + Dv);
            float v1 = 0.5f * (A + Bv - Cv - Dv);
            float v2 = 0.5f * (A - Bv + Cv - Dv);
            float v3 = 0.5f * (A + Bv + Cv + Dv);
            float h0 = h_hi_f(v0), h1 = h_hi_f(v1), h2 = h_hi_f(v2), h3 = h_hi_f(v3);
            uint32_t* yh = (uint32_t*)(smem + OFF_YHI + k * YROW_B);
            uint32_t* yl = (uint32_t*)(smem + OFF_YLO + k * YROW_B);
            yh[u]      = pack_h2(h0, h1);
            yh[32 + u] = pack_h2(h2, h3);
            yl[u]      = pack_h2(v0 - h0, v1 - h1);
            yl[32 + u] = pack_h2(v2 - h2, v3 - h3);
        }
    }

    // prefetch for chunk c+1 (x2 then x3): 8 eager + 4 late
    float4 pf[8];
    {
        #pragma unroll
        for (int it = 0; it < 8; ++it) {
            int q = tid + it * NTH;
            int k = q >> 5, p4 = q & 31, rr = p4 >> 4, c4 = p4 & 15;
            pf[it] = *(const float4*)(x2 + rowbase + k * CHS + rr * W_N + c4 * 4);
        }
    }
    __syncthreads();

    for (int chunk = 0; chunk < 3; ++chunk) {
        // ---- GEMM over chunk: 6 k-steps of 16, 2 fp16 passes ----
        #pragma unroll
        for (int ksl = 0; ksl < KSL; ++ksl) {
            uint32_t kadd = (uint32_t)(ksl * 16 * YROW_B);
            uint32_t ah[2][4], al[2][4];
            ldsm4t(ah[0], sb + OFF_YHI + kadd + lmoff0);
            ldsm4t(ah[1], sb + OFF_YHI + kadd + lmoff1);
            ldsm4t(al[0], sb + OFF_YLO + kadd + lmoff0);
            ldsm4t(al[1], sb + OFF_YLO + kadd + lmoff1);
            int kg = chunk * KSL + ksl;
            const uint4* wf = (const uint4*)(smem + OFF_W) + (kg * 6 + oh * 3) * 32 + lane;
            #pragma unroll
            for (int p = 0; p < 3; ++p) {
                uint4 wv = wf[p * 32];
                #pragma unroll
                for (int mt = 0; mt < 2; ++mt) {
                    mma16816(d[mt][2 * p],     ah[mt], wv.x, wv.y);
                    mma16816(d[mt][2 * p],     al[mt], wv.x, wv.y);
                    mma16816(d[mt][2 * p + 1], ah[mt], wv.z, wv.w);
                    mma16816(d[mt][2 * p + 1], al[mt], wv.z, wv.w);
                }
            }
        }
        if (chunk == 2) break;

        __syncthreads();   // all warps done reading Y buffer

        // ---- STS prefetched chunk+1, issue late loads, refill prefetch ----
        const float* xs_next = (chunk == 0) ? x3 : nullptr;  // refill source
        {
            #pragma unroll
            for (int it = 0; it < 8; ++it) {
                int q = tid + it * NTH;
                int k = q >> 5, p4 = q & 31, rr = p4 >> 4, c4 = p4 & 15;
                float4 v = pf[it];
                float h0 = h_hi_f(v.x), h1 = h_hi_f(v.y), h2 = h_hi_f(v.z), h3 = h_hi_f(v.w);
                int pp = (rr * 64 + c4 * 4) >> 1;
                uint32_t* yh = (uint32_t*)(smem + OFF_YHI + k * YROW_B);
                uint32_t* yl = (uint32_t*)(smem + OFF_YLO + k * YROW_B);
                *(uint2*)(yh + pp) = make_uint2(pack_h2(h0, h1), pack_h2(h2, h3));
                *(uint2*)(yl + pp) = make_uint2(pack_h2(v.x - h0, v.y - h1),
                                                pack_h2(v.z - h2, v.w - h3));
            }
            const float* xs = (chunk == 0) ? x2 : x3;
            float4 late[4];
            #pragma unroll
            for (int it = 0; it < 4; ++it) {
                int q = tid + (8 + it) * NTH;
                int k = q >> 5, p4 = q & 31, rr = p4 >> 4, c4 = p4 & 15;
                late[it] = *(const float4*)(xs + rowbase + k * CHS + rr * W_N + c4 * 4);
            }
            // refill eager prefetch for the chunk after next
            if (xs_next) {
                #pragma unroll
                for (int it = 0; it < 8; ++it) {
                    int q = tid + it * NTH;
                    int k = q >> 5, p4 = q & 31, rr = p4 >> 4, c4 = p4 & 15;
                    pf[it] = *(const float4*)(xs_next + rowbase + k * CHS + rr * W_N + c4 * 4);
                }
            }
            #pragma unroll
            for (int it = 0; it < 4; ++it) {
                int q = tid + (8 + it) * NTH;
                int k = q >> 5, p4 = q & 31, rr = p4 >> 4, c4 = p4 & 15;
                float4 v = late[it];
                float h0 = h_hi_f(v.x), h1 = h_hi_f(v.y), h2 = h_hi_f(v.z), h3 = h_hi_f(v.w);
                int pp = (rr * 64 + c4 * 4) >> 1;
                uint32_t* yh = (uint32_t*)(smem + OFF_YHI + k * YROW_B);
                uint32_t* yl = (uint32_t*)(smem + OFF_YLO + k * YROW_B);
                *(uint2*)(yh + pp) = make_uint2(pack_h2(h0, h1), pack_h2(h2, h3));
                *(uint2*)(yl + pp) = make_uint2(pack_h2(v.x - h0, v.y - h1),
                                                pack_h2(v.z - h2, v.w - h3));
            }
        }
        __syncthreads();
    }

    // ---- epilogue ----
    {
        const int g = lane >> 2, t = lane & 3;
        const int prow = pg >> 1;
        const int pcolb = (pg & 1) * 32;
        #pragma unroll
        for (int mt = 0; mt < 2; ++mt) {
            float* ob = out + ((size_t)(b * C_N + oh * 48) * H_N + 2 * r + prow) * W_N
                        + j0 + pcolb + mt * 16 + g;
            #pragma unroll
            for (int nt = 0; nt < 6; ++nt) {
                float* oc = ob + (size_t)(nt * 8 + 2 * t) * CHS;
                oc[0]       = d[mt][nt][0];
                oc[CHS]     = d[mt][nt][1];
                oc[8]       = d[mt][nt][2];
                oc[CHS + 8] = d[mt][nt][3];
            }
        }
    }
}

// ---------------- launch ----------------
extern "C" void kernel_launch(void* const* d_in, const int* in_sizes, int n_in,
                              void* d_out, int out_size) {
    const float* xs[3];
    const float* w = nullptr;
    int nx = 0;
    for (int i = 0; i < n_in; ++i) {
        if (in_sizes[i] == C_N * 288) w = (const float*)d_in[i];
        else if (nx < 3) xs[nx++] = (const float*)d_in[i];
    }
    float* out = (float*)d_out;

    cudaFuncSetAttribute(fused_mma_kernel,
                         cudaFuncAttributeMaxDynamicSharedMemorySize, SMEM_SZ);

    prep_w_kernel<<<(KSTEPS * 6 * 32 + 255) / 256, 256>>>(w);
    fused_mma_kernel<<<B_N * 128 * 4, NTH, SMEM_SZ>>>(xs[0], xs[1], xs[2], out);
}

// round 6
// speedup vs baseline: 3.0219x; 1.1810x over previous
#include <cuda_runtime.h>
#include <cuda_fp16.h>
#include <stdint.h>

// ---------------- problem constants ----------------
#define B_N 4
#define C_N 96
#define H_N 256
#define W_N 256
#define CHS (H_N * W_N)
#define NTH 256
#define KSTEPS 18            // 288 / 16
#define KSL 6                // k-steps per 96-channel chunk
#define YSTR 136             // halves per Y row (128 + 8 pad) -> 272B

// smem layout (bytes)
#define YROW_B (YSTR * 2)                 // 272
#define YSZ (96 * YROW_B)                 // 26112 per version
#define OFF_YHI 0
#define OFF_YLO YSZ                       // 26112 (used by chunk 0 only)
#define OFF_W  (2 * YSZ)                  // 52224
#define WSZ (KSTEPS * 6 * 32 * 16)        // 55296 (all k-steps)
#define SMEM_SZ (OFF_W + WSZ)             // 107520

// W fragments: [kstep][pair q=0..5][lane] uint4 =
//   {b0(nt=2q), b1(2q), b0(2q+1), b1(2q+1)}
__device__ uint4 g_Wf[KSTEPS * 6 * 32];

// ---------------- helpers ----------------
static __device__ __forceinline__ uint32_t smem_u32(const void* p) {
    uint32_t a;
    asm("{ .reg .u64 t; cvta.to.shared.u64 t, %1; cvt.u32.u64 %0, t; }" : "=r"(a) : "l"(p));
    return a;
}
static __device__ __forceinline__ uint32_t pack_h2(float a, float b) {
    __half2 h = __floats2half2_rn(a, b);
    return *(uint32_t*)&h;
}
static __device__ __forceinline__ float h_hi_f(float v) {
    return __half2float(__float2half_rn(v));
}
static __device__ __forceinline__ void ldsm4t(uint32_t* r, uint32_t addr) {
    asm volatile("ldmatrix.sync.aligned.m8n8.x4.trans.shared.b16 {%0,%1,%2,%3}, [%4];"
                 : "=r"(r[0]), "=r"(r[1]), "=r"(r[2]), "=r"(r[3]) : "r"(addr));
}
static __device__ __forceinline__ void mma16816(float* d, const uint32_t* a,
                                                uint32_t b0, uint32_t b1) {
    asm volatile(
        "mma.sync.aligned.m16n8k16.row.col.f32.f16.f16.f32 "
        "{%0,%1,%2,%3}, {%4,%5,%6,%7}, {%8,%9}, {%0,%1,%2,%3};"
        : "+f"(d[0]), "+f"(d[1]), "+f"(d[2]), "+f"(d[3])
        : "r"(a[0]), "r"(a[1]), "r"(a[2]), "r"(a[3]), "r"(b0), "r"(b1));
}
static __device__ __forceinline__ float ffm_sel(float a, float b) {
    return (fabsf(a) >= fabsf(b)) ? a : b;
}

// ---------------- prep: W -> per-lane fp16 B fragments ----------------
__global__ void prep_w_kernel(const float* __restrict__ w) {
    int i = blockIdx.x * 256 + threadIdx.x;
    if (i >= KSTEPS * 6 * 32) return;
    int lane = i & 31;
    int q = (i >> 5) % 6;
    int ks = i / (6 * 32);
    int t = lane & 3;
    int g = lane >> 2;
    int k0 = ks * 16;
    int oe = (2 * q) * 8 + g;
    int oo = (2 * q + 1) * 8 + g;
    uint4 v;
    v.x = pack_h2(w[oe * 288 + k0 + 2 * t],     w[oe * 288 + k0 + 2 * t + 1]);
    v.y = pack_h2(w[oe * 288 + k0 + 2 * t + 8], w[oe * 288 + k0 + 2 * t + 9]);
    v.z = pack_h2(w[oo * 288 + k0 + 2 * t],     w[oo * 288 + k0 + 2 * t + 1]);
    v.w = pack_h2(w[oo * 288 + k0 + 2 * t + 8], w[oo * 288 + k0 + 2 * t + 9]);
    g_Wf[i] = v;
}

// ---------------- fused DWT + concat + 1x1 conv, pipelined mma.sync ----------------
__global__ void __launch_bounds__(NTH, 2)
fused_mma_kernel(const float* __restrict__ x1, const float* __restrict__ x2,
                 const float* __restrict__ x3, float* __restrict__ out) {
    extern __shared__ unsigned char smem[];
    const uint32_t sb = smem_u32(smem);

    const int tid = threadIdx.x;
    const int wid = tid >> 5;
    const int lane = tid & 31;
    const int bid = blockIdx.x;
    const int b  = bid >> 9;
    const int r  = (bid >> 2) & 127;
    const int j0 = (bid & 3) << 6;

    const int pg = wid & 3;             // pixel group (32 pixels)
    const int oh = wid >> 2;            // output half (48 outs)
    const int pixb = pg * 32;

    const int g2 = lane >> 3, jj = lane & 7;
    const int krow = ((g2 & 2) << 2) + jj;
    const int pxo  = (g2 & 1) << 3;
    const uint32_t lmoff0 = (uint32_t)(krow * YSTR + pixb + pxo) * 2;
    const uint32_t lmoff1 = lmoff0 + 32;

    float d[2][6][4];
    #pragma unroll
    for (int mt = 0; mt < 2; ++mt)
        #pragma unroll
        for (int nt = 0; nt < 6; ++nt)
            #pragma unroll
            for (int q = 0; q < 4; ++q) d[mt][nt][q] = 0.0f;

    const int rowbase = ((b * C_N) * H_N + 2 * r) * W_N + j0;

    // ---- stage ALL W fragments once ----
    {
        const uint4* src = g_Wf;
        uint4* dst = (uint4*)(smem + OFF_W);
        #pragma unroll
        for (int i = tid; i < KSTEPS * 6 * 32; i += NTH) dst[i] = src[i];
    }

    // ---- chunk0 staging: DWT -> ffm -> IDWT (hi + lo) ----
    {
        #pragma unroll 4
        for (int it = 0; it < 12; ++it) {
            int q = tid + it * NTH;
            int k = q >> 5;
            int u = q & 31;
            int off = rowbase + k * CHS + 2 * u;
            float2 t1 = *(const float2*)(x1 + off);
            float2 g1 = *(const float2*)(x1 + off + W_N);
            float2 t2 = *(const float2*)(x2 + off);
            float2 g2v = *(const float2*)(x2 + off + W_N);
            float2 t3 = *(const float2*)(x3 + off);
            float2 g3 = *(const float2*)(x3 + off + W_N);
            float s1, s2, w1, w2;
            s1 = t1.x + g1.x; s2 = t1.y + g1.y; w1 = g1.x - t1.x; w2 = g1.y - t1.y;
            float A1 = 0.5f*(s1+s2), B1 = 0.5f*(s2-s1), C1 = 0.5f*(w1+w2), D1 = 0.5f*(w2-w1);
            s1 = t2.x + g2v.x; s2 = t2.y + g2v.y; w1 = g2v.x - t2.x; w2 = g2v.y - t2.y;
            float A2 = 0.5f*(s1+s2), B2 = 0.5f*(s2-s1), C2 = 0.5f*(w1+w2), D2 = 0.5f*(w2-w1);
            s1 = t3.x + g3.x; s2 = t3.y + g3.y; w1 = g3.x - t3.x; w2 = g3.y - t3.y;
            float A3 = 0.5f*(s1+s2), B3 = 0.5f*(s2-s1), C3 = 0.5f*(w1+w2), D3 = 0.5f*(w2-w1);
            float A  = (A1 + A2 + A3) * (1.0f / 3.0f);
            float Bv = ffm_sel(ffm_sel(B1, B2), B3);
            float Cv = ffm_sel(ffm_sel(C1, C2), C3);
            float Dv = ffm_sel(ffm_sel(D1, D2), D3);
            float v0 = 0.5f * (A - Bv - Cv + Dv);
            float v1 = 0.5f * (A + Bv - Cv - Dv);
            float v2 = 0.5f * (A - Bv + Cv - Dv);
            float v3 = 0.5f * (A + Bv + Cv + Dv);
            float h0 = h_hi_f(v0), h1 = h_hi_f(v1), h2 = h_hi_f(v2), h3 = h_hi_f(v3);
            uint32_t* yh = (uint32_t*)(smem + OFF_YHI + k * YROW_B);
            uint32_t* yl = (uint32_t*)(smem + OFF_YLO + k * YROW_B);
            yh[u]      = pack_h2(h0, h1);
            yh[32 + u] = pack_h2(h2, h3);
            yl[u]      = pack_h2(v0 - h0, v1 - h1);
            yl[32 + u] = pack_h2(v2 - h2, v3 - h3);
        }
    }

    // prefetch for chunk c+1: 8 eager + 4 late
    float4 pf[8];
    {
        #pragma unroll
        for (int it = 0; it < 8; ++it) {
            int q = tid + it * NTH;
            int k = q >> 5, p4 = q & 31, rr = p4 >> 4, c4 = p4 & 15;
            pf[it] = *(const float4*)(x2 + rowbase + k * CHS + rr * W_N + c4 * 4);
        }
    }
    __syncthreads();

    // ================= GEMM chunk 0: 2-pass (hi + lo) =================
    #pragma unroll
    for (int ksl = 0; ksl < KSL; ++ksl) {
        uint32_t kadd = (uint32_t)(ksl * 16 * YROW_B);
        uint32_t ah[2][4], al[2][4];
        ldsm4t(ah[0], sb + OFF_YHI + kadd + lmoff0);
        ldsm4t(ah[1], sb + OFF_YHI + kadd + lmoff1);
        ldsm4t(al[0], sb + OFF_YLO + kadd + lmoff0);
        ldsm4t(al[1], sb + OFF_YLO + kadd + lmoff1);
        const uint4* wf = (const uint4*)(smem + OFF_W) + (ksl * 6 + oh * 3) * 32 + lane;
        #pragma unroll
        for (int p = 0; p < 3; ++p) {
            uint4 wv = wf[p * 32];
            #pragma unroll
            for (int mt = 0; mt < 2; ++mt) {
                mma16816(d[mt][2 * p],     ah[mt], wv.x, wv.y);
                mma16816(d[mt][2 * p],     al[mt], wv.x, wv.y);
                mma16816(d[mt][2 * p + 1], ah[mt], wv.z, wv.w);
                mma16816(d[mt][2 * p + 1], al[mt], wv.z, wv.w);
            }
        }
    }

    // ================= chunks 1,2: hi-only (1-pass) =================
    #pragma unroll
    for (int chunk = 1; chunk < 3; ++chunk) {
        __syncthreads();   // all warps done reading Y buffer

        // ---- STS prefetched chunk (hi only), late loads, refill prefetch ----
        {
            #pragma unroll
            for (int it = 0; it < 8; ++it) {
                int q = tid + it * NTH;
                int k = q >> 5, p4 = q & 31, rr = p4 >> 4, c4 = p4 & 15;
                float4 v = pf[it];
                int pp = (rr * 64 + c4 * 4) >> 1;
                uint32_t* yh = (uint32_t*)(smem + OFF_YHI + k * YROW_B);
                *(uint2*)(yh + pp) = make_uint2(pack_h2(v.x, v.y), pack_h2(v.z, v.w));
            }
            const float* xs = (chunk == 1) ? x2 : x3;
            float4 late[4];
            #pragma unroll
            for (int it = 0; it < 4; ++it) {
                int q = tid + (8 + it) * NTH;
                int k = q >> 5, p4 = q & 31, rr = p4 >> 4, c4 = p4 & 15;
                late[it] = *(const float4*)(xs + rowbase + k * CHS + rr * W_N + c4 * 4);
            }
            if (chunk == 1) {
                #pragma unroll
                for (int it = 0; it < 8; ++it) {
                    int q = tid + it * NTH;
                    int k = q >> 5, p4 = q & 31, rr = p4 >> 4, c4 = p4 & 15;
                    pf[it] = *(const float4*)(x3 + rowbase + k * CHS + rr * W_N + c4 * 4);
                }
            }
            #pragma unroll
            for (int it = 0; it < 4; ++it) {
                int q = tid + (8 + it) * NTH;
                int k = q >> 5, p4 = q & 31, rr = p4 >> 4, c4 = p4 & 15;
                float4 v = late[it];
                int pp = (rr * 64 + c4 * 4) >> 1;
                uint32_t* yh = (uint32_t*)(smem + OFF_YHI + k * YROW_B);
                *(uint2*)(yh + pp) = make_uint2(pack_h2(v.x, v.y), pack_h2(v.z, v.w));
            }
        }
        __syncthreads();

        // ---- GEMM: 6 k-steps, 1 pass ----
        #pragma unroll
        for (int ksl = 0; ksl < KSL; ++ksl) {
            uint32_t kadd = (uint32_t)(ksl * 16 * YROW_B);
            uint32_t ah[2][4];
            ldsm4t(ah[0], sb + OFF_YHI + kadd + lmoff0);
            ldsm4t(ah[1], sb + OFF_YHI + kadd + lmoff1);
            int kg = chunk * KSL + ksl;
            const uint4* wf = (const uint4*)(smem + OFF_W) + (kg * 6 + oh * 3) * 32 + lane;
            #pragma unroll
            for (int p = 0; p < 3; ++p) {
                uint4 wv = wf[p * 32];
                #pragma unroll
                for (int mt = 0; mt < 2; ++mt) {
                    mma16816(d[mt][2 * p],     ah[mt], wv.x, wv.y);
                    mma16816(d[mt][2 * p + 1], ah[mt], wv.z, wv.w);
                }
            }
        }
    }

    // ---- epilogue ----
    {
        const int g = lane >> 2, t = lane & 3;
        const int prow = pg >> 1;
        const int pcolb = (pg & 1) * 32;
        #pragma unroll
        for (int mt = 0; mt < 2; ++mt) {
            float* ob = out + ((size_t)(b * C_N + oh * 48) * H_N + 2 * r + prow) * W_N
                        + j0 + pcolb + mt * 16 + g;
            #pragma unroll
            for (int nt = 0; nt < 6; ++nt) {
                float* oc = ob + (size_t)(nt * 8 + 2 * t) * CHS;
                oc[0]       = d[mt][nt][0];
                oc[CHS]     = d[mt][nt][1];
                oc[8]       = d[mt][nt][2];
                oc[CHS + 8] = d[mt][nt][3];
            }
        }
    }
}

// ---------------- launch ----------------
extern "C" void kernel_launch(void* const* d_in, const int* in_sizes, int n_in,
                              void* d_out, int out_size) {
    const float* xs[3];
    const float* w = nullptr;
    int nx = 0;
    for (int i = 0; i < n_in; ++i) {
        if (in_sizes[i] == C_N * 288) w = (const float*)d_in[i];
        else if (nx < 3) xs[nx++] = (const float*)d_in[i];
    }
    float* out = (float*)d_out;

    cudaFuncSetAttribute(fused_mma_kernel,
                         cudaFuncAttributeMaxDynamicSharedMemorySize, SMEM_SZ);

    prep_w_kernel<<<(KSTEPS * 6 * 32 + 255) / 256, 256>>>(w);
    fused_mma_kernel<<<B_N * 128 * 4, NTH, SMEM_SZ>>>(xs[0], xs[1], xs[2], out);
}

// round 7
// speedup vs baseline: 3.3129x; 1.0963x over previous
#include <cuda_runtime.h>
#include <cuda_fp16.h>
#include <stdint.h>

// ---------------- problem constants ----------------
#define B_N 4
#define C_N 96
#define H_N 256
#define W_N 256
#define CHS (H_N * W_N)
#define NTH 256
#define KSTEPS 18            // 288 / 16
#define YSTR 136             // halves per Y row (128 + 8 pad) -> 272B

// smem layout (bytes): chunk0 hi, chunk0 lo, chunk1 hi, chunk2 hi
#define YROW_B (YSTR * 2)                 // 272
#define YSZ (96 * YROW_B)                 // 26112
#define OFF_Y0H 0
#define OFF_Y0L YSZ                       // 26112
#define OFF_Y1  (2 * YSZ)                 // 52224
#define OFF_Y2  (3 * YSZ)                 // 78336
#define SMEM_SZ (4 * YSZ)                 // 104448

// W fragments: [kstep][pair q=0..5][lane] uint4 =
//   {b0(nt=2q), b1(2q), b0(2q+1), b1(2q+1)}  -- read directly from gmem (L1-hot)
__device__ uint4 g_Wf[KSTEPS * 6 * 32];

// ---------------- helpers ----------------
static __device__ __forceinline__ uint32_t smem_u32(const void* p) {
    uint32_t a;
    asm("{ .reg .u64 t; cvta.to.shared.u64 t, %1; cvt.u32.u64 %0, t; }" : "=r"(a) : "l"(p));
    return a;
}
static __device__ __forceinline__ uint32_t pack_h2(float a, float b) {
    __half2 h = __floats2half2_rn(a, b);
    return *(uint32_t*)&h;
}
static __device__ __forceinline__ float h_hi_f(float v) {
    return __half2float(__float2half_rn(v));
}
static __device__ __forceinline__ void ldsm4t(uint32_t* r, uint32_t addr) {
    asm volatile("ldmatrix.sync.aligned.m8n8.x4.trans.shared.b16 {%0,%1,%2,%3}, [%4];"
                 : "=r"(r[0]), "=r"(r[1]), "=r"(r[2]), "=r"(r[3]) : "r"(addr));
}
static __device__ __forceinline__ void mma16816(float* d, const uint32_t* a,
                                                uint32_t b0, uint32_t b1) {
    asm volatile(
        "mma.sync.aligned.m16n8k16.row.col.f32.f16.f16.f32 "
        "{%0,%1,%2,%3}, {%4,%5,%6,%7}, {%8,%9}, {%0,%1,%2,%3};"
        : "+f"(d[0]), "+f"(d[1]), "+f"(d[2]), "+f"(d[3])
        : "r"(a[0]), "r"(a[1]), "r"(a[2]), "r"(a[3]), "r"(b0), "r"(b1));
}
static __device__ __forceinline__ float ffm_sel(float a, float b) {
    return (fabsf(a) >= fabsf(b)) ? a : b;
}

// ---------------- prep: W -> per-lane fp16 B fragments ----------------
__global__ void prep_w_kernel(const float* __restrict__ w) {
    int i = blockIdx.x * 256 + threadIdx.x;
    if (i >= KSTEPS * 6 * 32) return;
    int lane = i & 31;
    int q = (i >> 5) % 6;
    int ks = i / (6 * 32);
    int t = lane & 3;
    int g = lane >> 2;
    int k0 = ks * 16;
    int oe = (2 * q) * 8 + g;
    int oo = (2 * q + 1) * 8 + g;
    uint4 v;
    v.x = pack_h2(w[oe * 288 + k0 + 2 * t],     w[oe * 288 + k0 + 2 * t + 1]);
    v.y = pack_h2(w[oe * 288 + k0 + 2 * t + 8], w[oe * 288 + k0 + 2 * t + 9]);
    v.z = pack_h2(w[oo * 288 + k0 + 2 * t],     w[oo * 288 + k0 + 2 * t + 1]);
    v.w = pack_h2(w[oo * 288 + k0 + 2 * t + 8], w[oo * 288 + k0 + 2 * t + 9]);
    g_Wf[i] = v;
}

// ---------------- fused DWT + concat + 1x1 conv: single-stage + long GEMM ----------------
__global__ void __launch_bounds__(NTH, 2)
fused_mma_kernel(const float* __restrict__ x1, const float* __restrict__ x2,
                 const float* __restrict__ x3, float* __restrict__ out) {
    extern __shared__ unsigned char smem[];
    const uint32_t sb = smem_u32(smem);

    const int tid = threadIdx.x;
    const int wid = tid >> 5;
    const int lane = tid & 31;
    const int bid = blockIdx.x;
    const int b  = bid >> 9;
    const int r  = (bid >> 2) & 127;
    const int j0 = (bid & 3) << 6;

    const int pg = wid & 3;             // pixel group (32 pixels)
    const int oh = wid >> 2;            // output half (48 outs)
    const int pixb = pg * 32;

    const int g2i = lane >> 3, jj = lane & 7;
    const int krow = ((g2i & 2) << 2) + jj;
    const int pxo  = (g2i & 1) << 3;
    const uint32_t lmoff0 = (uint32_t)(krow * YSTR + pixb + pxo) * 2;
    const uint32_t lmoff1 = lmoff0 + 32;

    float d[2][6][4];
    #pragma unroll
    for (int mt = 0; mt < 2; ++mt)
        #pragma unroll
        for (int nt = 0; nt < 6; ++nt)
            #pragma unroll
            for (int q = 0; q < 4; ++q) d[mt][nt][q] = 0.0f;

    const int rowbase = ((b * C_N) * H_N + 2 * r) * W_N + j0;

    // ---- single staging pass: DWT chunk plus raw x2/x3 hi images ----
    {
        #pragma unroll 4
        for (int it = 0; it < 12; ++it) {
            int q = tid + it * NTH;
            int k = q >> 5;
            int u = q & 31;
            int off = rowbase + k * CHS + 2 * u;
            float2 t1 = *(const float2*)(x1 + off);
            float2 g1 = *(const float2*)(x1 + off + W_N);
            float2 t2 = *(const float2*)(x2 + off);
            float2 g2v = *(const float2*)(x2 + off + W_N);
            float2 t3 = *(const float2*)(x3 + off);
            float2 g3 = *(const float2*)(x3 + off + W_N);

            // chunk1/chunk2 images (hi-only fp16), written from the same registers
            uint32_t* y1 = (uint32_t*)(smem + OFF_Y1 + k * YROW_B);
            uint32_t* y2 = (uint32_t*)(smem + OFF_Y2 + k * YROW_B);
            y1[u]      = pack_h2(t2.x, t2.y);
            y1[32 + u] = pack_h2(g2v.x, g2v.y);
            y2[u]      = pack_h2(t3.x, t3.y);
            y2[32 + u] = pack_h2(g3.x, g3.y);

            // DWT -> ffm -> IDWT for x_rec (chunk0, hi+lo split)
            float s1, s2, w1, w2;
            s1 = t1.x + g1.x; s2 = t1.y + g1.y; w1 = g1.x - t1.x; w2 = g1.y - t1.y;
            float A1 = 0.5f*(s1+s2), B1 = 0.5f*(s2-s1), C1 = 0.5f*(w1+w2), D1 = 0.5f*(w2-w1);
            s1 = t2.x + g2v.x; s2 = t2.y + g2v.y; w1 = g2v.x - t2.x; w2 = g2v.y - t2.y;
            float A2 = 0.5f*(s1+s2), B2 = 0.5f*(s2-s1), C2 = 0.5f*(w1+w2), D2 = 0.5f*(w2-w1);
            s1 = t3.x + g3.x; s2 = t3.y + g3.y; w1 = g3.x - t3.x; w2 = g3.y - t3.y;
            float A3 = 0.5f*(s1+s2), B3 = 0.5f*(s2-s1), C3 = 0.5f*(w1+w2), D3 = 0.5f*(w2-w1);
            float A  = (A1 + A2 + A3) * (1.0f / 3.0f);
            float Bv = ffm_sel(ffm_sel(B1, B2), B3);
            float Cv = ffm_sel(ffm_sel(C1, C2), C3);
            float Dv = ffm_sel(ffm_sel(D1, D2), D3);
            float v0 = 0.5f * (A - Bv - Cv + Dv);
            float v1 = 0.5f * (A + Bv - Cv - Dv);
            float v2 = 0.5f * (A - Bv + Cv - Dv);
            float v3 = 0.5f * (A + Bv + Cv + Dv);
            float h0 = h_hi_f(v0), h1 = h_hi_f(v1), h2 = h_hi_f(v2), h3 = h_hi_f(v3);
            uint32_t* yh = (uint32_t*)(smem + OFF_Y0H + k * YROW_B);
            uint32_t* yl = (uint32_t*)(smem + OFF_Y0L + k * YROW_B);
            yh[u]      = pack_h2(h0, h1);
            yh[32 + u] = pack_h2(h2, h3);
            yl[u]      = pack_h2(v0 - h0, v1 - h1);
            yl[32 + u] = pack_h2(v2 - h2, v3 - h3);
        }
    }
    __syncthreads();

    // ---- one long GEMM: 18 k-steps; chunk0 = 2-pass (hi+lo), chunks 1/2 = hi-only ----
    // W fragments read directly from gmem, software-pipelined one k-step ahead.
    const uint4* wbase = g_Wf + oh * 3 * 32 + lane;
    uint4 wc0 = __ldg(wbase);
    uint4 wc1 = __ldg(wbase + 32);
    uint4 wc2 = __ldg(wbase + 64);

    #pragma unroll
    for (int ks = 0; ks < KSTEPS; ++ks) {
        const int chunk = ks / 6;
        const int ksl = ks % 6;
        const uint32_t ybase = (chunk == 0) ? OFF_Y0H : (chunk == 1) ? OFF_Y1 : OFF_Y2;
        const uint32_t kadd = (uint32_t)(ksl * 16 * YROW_B);

        uint4 wn0, wn1, wn2;
        if (ks + 1 < KSTEPS) {
            const uint4* wnx = wbase + (ks + 1) * 192;
            wn0 = __ldg(wnx);
            wn1 = __ldg(wnx + 32);
            wn2 = __ldg(wnx + 64);
        }

        uint32_t ah[2][4];
        ldsm4t(ah[0], sb + ybase + kadd + lmoff0);
        ldsm4t(ah[1], sb + ybase + kadd + lmoff1);

        if (chunk == 0) {
            uint32_t al[2][4];
            ldsm4t(al[0], sb + OFF_Y0L + kadd + lmoff0);
            ldsm4t(al[1], sb + OFF_Y0L + kadd + lmoff1);
            #pragma unroll
            for (int mt = 0; mt < 2; ++mt) {
                mma16816(d[mt][0], ah[mt], wc0.x, wc0.y);
                mma16816(d[mt][0], al[mt], wc0.x, wc0.y);
                mma16816(d[mt][1], ah[mt], wc0.z, wc0.w);
                mma16816(d[mt][1], al[mt], wc0.z, wc0.w);
                mma16816(d[mt][2], ah[mt], wc1.x, wc1.y);
                mma16816(d[mt][2], al[mt], wc1.x, wc1.y);
                mma16816(d[mt][3], ah[mt], wc1.z, wc1.w);
                mma16816(d[mt][3], al[mt], wc1.z, wc1.w);
                mma16816(d[mt][4], ah[mt], wc2.x, wc2.y);
                mma16816(d[mt][4], al[mt], wc2.x, wc2.y);
                mma16816(d[mt][5], ah[mt], wc2.z, wc2.w);
                mma16816(d[mt][5], al[mt], wc2.z, wc2.w);
            }
        } else {
            #pragma unroll
            for (int mt = 0; mt < 2; ++mt) {
                mma16816(d[mt][0], ah[mt], wc0.x, wc0.y);
                mma16816(d[mt][1], ah[mt], wc0.z, wc0.w);
                mma16816(d[mt][2], ah[mt], wc1.x, wc1.y);
                mma16816(d[mt][3], ah[mt], wc1.z, wc1.w);
                mma16816(d[mt][4], ah[mt], wc2.x, wc2.y);
                mma16816(d[mt][5], ah[mt], wc2.z, wc2.w);
            }
        }
        wc0 = wn0; wc1 = wn1; wc2 = wn2;
    }

    // ---- epilogue ----
    {
        const int g = lane >> 2, t = lane & 3;
        const int prow = pg >> 1;
        const int pcolb = (pg & 1) * 32;
        #pragma unroll
        for (int mt = 0; mt < 2; ++mt) {
            float* ob = out + ((size_t)(b * C_N + oh * 48) * H_N + 2 * r + prow) * W_N
                        + j0 + pcolb + mt * 16 + g;
            #pragma unroll
            for (int nt = 0; nt < 6; ++nt) {
                float* oc = ob + (size_t)(nt * 8 + 2 * t) * CHS;
                oc[0]       = d[mt][nt][0];
                oc[CHS]     = d[mt][nt][1];
                oc[8]       = d[mt][nt][2];
                oc[CHS + 8] = d[mt][nt][3];
            }
        }
    }
}

// ---------------- launch ----------------
extern "C" void kernel_launch(void* const* d_in, const int* in_sizes, int n_in,
                              void* d_out, int out_size) {
    const float* xs[3];
    const float* w = nullptr;
    int nx = 0;
    for (int i = 0; i < n_in; ++i) {
        if (in_sizes[i] == C_N * 288) w = (const float*)d_in[i];
        else if (nx < 3) xs[nx++] = (const float*)d_in[i];
    }
    float* out = (float*)d_out;

    cudaFuncSetAttribute(fused_mma_kernel,
                         cudaFuncAttributeMaxDynamicSharedMemorySize, SMEM_SZ);

    prep_w_kernel<<<(KSTEPS * 6 * 32 + 255) / 256, 256>>>(w);
    fused_mma_kernel<<<B_N * 128 * 4, NTH, SMEM_SZ>>>(xs[0], xs[1], xs[2], out);
}

// round 8
// speedup vs baseline: 4.2242x; 1.2751x over previous
#include <cuda_runtime.h>
#include <cuda_fp16.h>
#include <stdint.h>

// ---------------- problem constants ----------------
#define B_N 4
#define C_N 96
#define H_N 256
#define W_N 256
#define CHS (H_N * W_N)
#define NTH 128
#define KSTEPS 18            // 288 / 16

// Y tile: 96 k-rows x 64 pixels (2 image rows x 32 cols), fp16
#define YSTR 72              // halves per row (64 + 8 pad) -> 144B = 9*16B
#define YROW_B (YSTR * 2)    // 144
#define YSZ (96 * YROW_B)    // 13824
#define OFF_Y0 0
#define OFF_Y1 YSZ           // 13824
#define OFF_Y2 (2 * YSZ)     // 27648
#define SMEM_SZ (3 * YSZ)    // 41472

// W fragments: [kstep][pair q=0..5][lane] uint4 =
//   {b0(nt=2q), b1(2q), b0(2q+1), b1(2q+1)}  -- read directly from gmem (L1-hot)
__device__ uint4 g_Wf[KSTEPS * 6 * 32];

// ---------------- helpers ----------------
static __device__ __forceinline__ uint32_t smem_u32(const void* p) {
    uint32_t a;
    asm("{ .reg .u64 t; cvta.to.shared.u64 t, %1; cvt.u32.u64 %0, t; }" : "=r"(a) : "l"(p));
    return a;
}
static __device__ __forceinline__ uint32_t pack_h2(float a, float b) {
    __half2 h = __floats2half2_rn(a, b);
    return *(uint32_t*)&h;
}
static __device__ __forceinline__ void ldsm4t(uint32_t* r, uint32_t addr) {
    asm volatile("ldmatrix.sync.aligned.m8n8.x4.trans.shared.b16 {%0,%1,%2,%3}, [%4];"
                 : "=r"(r[0]), "=r"(r[1]), "=r"(r[2]), "=r"(r[3]) : "r"(addr));
}
static __device__ __forceinline__ void mma16816(float* d, const uint32_t* a,
                                                uint32_t b0, uint32_t b1) {
    asm volatile(
        "mma.sync.aligned.m16n8k16.row.col.f32.f16.f16.f32 "
        "{%0,%1,%2,%3}, {%4,%5,%6,%7}, {%8,%9}, {%0,%1,%2,%3};"
        : "+f"(d[0]), "+f"(d[1]), "+f"(d[2]), "+f"(d[3])
        : "r"(a[0]), "r"(a[1]), "r"(a[2]), "r"(a[3]), "r"(b0), "r"(b1));
}
static __device__ __forceinline__ float ffm_sel(float a, float b) {
    return (fabsf(a) >= fabsf(b)) ? a : b;
}

// ---------------- prep: W -> per-lane fp16 B fragments ----------------
__global__ void prep_w_kernel(const float* __restrict__ w) {
    int i = blockIdx.x * 256 + threadIdx.x;
    if (i >= KSTEPS * 6 * 32) return;
    int lane = i & 31;
    int q = (i >> 5) % 6;
    int ks = i / (6 * 32);
    int t = lane & 3;
    int g = lane >> 2;
    int k0 = ks * 16;
    int oe = (2 * q) * 8 + g;
    int oo = (2 * q + 1) * 8 + g;
    uint4 v;
    v.x = pack_h2(w[oe * 288 + k0 + 2 * t],     w[oe * 288 + k0 + 2 * t + 1]);
    v.y = pack_h2(w[oe * 288 + k0 + 2 * t + 8], w[oe * 288 + k0 + 2 * t + 9]);
    v.z = pack_h2(w[oo * 288 + k0 + 2 * t],     w[oo * 288 + k0 + 2 * t + 1]);
    v.w = pack_h2(w[oo * 288 + k0 + 2 * t + 8], w[oo * 288 + k0 + 2 * t + 9]);
    g_Wf[i] = v;
}

// ---------------- fused DWT + concat + 1x1 conv: 64-pixel blocks, hi-only fp16 ----------------
__global__ void __launch_bounds__(NTH, 4)
fused_mma_kernel(const float* __restrict__ x1, const float* __restrict__ x2,
                 const float* __restrict__ x3, float* __restrict__ out) {
    extern __shared__ unsigned char smem[];
    const uint32_t sb = smem_u32(smem);

    const int tid = threadIdx.x;
    const int wid = tid >> 5;
    const int lane = tid & 31;
    const int bid = blockIdx.x;
    const int b  = bid >> 10;           // 1024 blocks per batch
    const int r  = (bid >> 3) & 127;    // row-pair index
    const int j0 = (bid & 7) << 5;      // col base: 0,32,...,224

    const int pg = wid & 1;             // image row within pair (32 pixels)
    const int oh = wid >> 1;            // output half (48 outs)

    const int g2i = lane >> 3, jj = lane & 7;
    const int krow = ((g2i & 2) << 2) + jj;
    const int pxo  = (g2i & 1) << 3;
    const uint32_t lmoff0 = (uint32_t)(krow * YSTR + pg * 32 + pxo) * 2;
    const uint32_t lmoff1 = lmoff0 + 32;   // mtile 1: +16 pixels

    const int rowbase = ((b * C_N) * H_N + 2 * r) * W_N + j0;

    // ---- single staging pass: 96 k x 16 col-pairs = 1536 units, 12/thread ----
    {
        #pragma unroll 4
        for (int it = 0; it < 12; ++it) {
            int q = tid + it * NTH;
            int k = q >> 4;
            int u = q & 15;
            int off = rowbase + k * CHS + 2 * u;
            float2 t1 = *(const float2*)(x1 + off);
            float2 g1 = *(const float2*)(x1 + off + W_N);
            float2 t2 = *(const float2*)(x2 + off);
            float2 g2v = *(const float2*)(x2 + off + W_N);
            float2 t3 = *(const float2*)(x3 + off);
            float2 g3 = *(const float2*)(x3 + off + W_N);

            // x2 / x3 hi images straight from registers
            uint32_t* y1 = (uint32_t*)(smem + OFF_Y1 + k * YROW_B);
            uint32_t* y2 = (uint32_t*)(smem + OFF_Y2 + k * YROW_B);
            y1[u]      = pack_h2(t2.x, t2.y);
            y1[16 + u] = pack_h2(g2v.x, g2v.y);
            y2[u]      = pack_h2(t3.x, t3.y);
            y2[16 + u] = pack_h2(g3.x, g3.y);

            // DWT -> ffm -> IDWT for x_rec (chunk0)
            float s1, s2, w1, w2;
            s1 = t1.x + g1.x; s2 = t1.y + g1.y; w1 = g1.x - t1.x; w2 = g1.y - t1.y;
            float A1 = 0.5f*(s1+s2), B1 = 0.5f*(s2-s1), C1 = 0.5f*(w1+w2), D1 = 0.5f*(w2-w1);
            s1 = t2.x + g2v.x; s2 = t2.y + g2v.y; w1 = g2v.x - t2.x; w2 = g2v.y - t2.y;
            float A2 = 0.5f*(s1+s2), B2 = 0.5f*(s2-s1), C2 = 0.5f*(w1+w2), D2 = 0.5f*(w2-w1);
            s1 = t3.x + g3.x; s2 = t3.y + g3.y; w1 = g3.x - t3.x; w2 = g3.y - t3.y;
            float A3 = 0.5f*(s1+s2), B3 = 0.5f*(s2-s1), C3 = 0.5f*(w1+w2), D3 = 0.5f*(w2-w1);
            float A  = (A1 + A2 + A3) * (1.0f / 3.0f);
            float Bv = ffm_sel(ffm_sel(B1, B2), B3);
            float Cv = ffm_sel(ffm_sel(C1, C2), C3);
            float Dv = ffm_sel(ffm_sel(D1, D2), D3);
            float v0 = 0.5f * (A - Bv - Cv + Dv);
            float v1 = 0.5f * (A + Bv - Cv - Dv);
            float v2 = 0.5f * (A - Bv + Cv - Dv);
            float v3 = 0.5f * (A + Bv + Cv + Dv);
            uint32_t* y0 = (uint32_t*)(smem + OFF_Y0 + k * YROW_B);
            y0[u]      = pack_h2(v0, v1);
            y0[16 + u] = pack_h2(v2, v3);
        }
    }
    __syncthreads();

    float d[2][6][4];
    #pragma unroll
    for (int mt = 0; mt < 2; ++mt)
        #pragma unroll
        for (int nt = 0; nt < 6; ++nt)
            #pragma unroll
            for (int q = 0; q < 4; ++q) d[mt][nt][q] = 0.0f;

    // ---- one long GEMM: 18 k-steps, hi-only; W pipelined from gmem (L1-hot) ----
    const uint4* wbase = g_Wf + oh * 3 * 32 + lane;
    uint4 wc0 = __ldg(wbase);
    uint4 wc1 = __ldg(wbase + 32);
    uint4 wc2 = __ldg(wbase + 64);

    #pragma unroll
    for (int ks = 0; ks < KSTEPS; ++ks) {
        const int chunk = ks / 6;
        const int ksl = ks % 6;
        const uint32_t ybase = (chunk == 0) ? OFF_Y0 : (chunk == 1) ? OFF_Y1 : OFF_Y2;
        const uint32_t kadd = (uint32_t)(ksl * 16 * YROW_B);

        uint4 wn0, wn1, wn2;
        if (ks + 1 < KSTEPS) {
            const uint4* wnx = wbase + (ks + 1) * 192;
            wn0 = __ldg(wnx);
            wn1 = __ldg(wnx + 32);
            wn2 = __ldg(wnx + 64);
        }

        uint32_t ah[2][4];
        ldsm4t(ah[0], sb + ybase + kadd + lmoff0);
        ldsm4t(ah[1], sb + ybase + kadd + lmoff1);

        #pragma unroll
        for (int mt = 0; mt < 2; ++mt) {
            mma16816(d[mt][0], ah[mt], wc0.x, wc0.y);
            mma16816(d[mt][1], ah[mt], wc0.z, wc0.w);
            mma16816(d[mt][2], ah[mt], wc1.x, wc1.y);
            mma16816(d[mt][3], ah[mt], wc1.z, wc1.w);
            mma16816(d[mt][4], ah[mt], wc2.x, wc2.y);
            mma16816(d[mt][5], ah[mt], wc2.z, wc2.w);
        }
        wc0 = wn0; wc1 = wn1; wc2 = wn2;
    }

    // ---- epilogue ----
    {
        const int g = lane >> 2, t = lane & 3;
        #pragma unroll
        for (int mt = 0; mt < 2; ++mt) {
            float* ob = out + ((size_t)(b * C_N + oh * 48) * H_N + 2 * r + pg) * W_N
                        + j0 + mt * 16 + g;
            #pragma unroll
            for (int nt = 0; nt < 6; ++nt) {
                float* oc = ob + (size_t)(nt * 8 + 2 * t) * CHS;
                oc[0]       = d[mt][nt][0];
                oc[CHS]     = d[mt][nt][1];
                oc[8]       = d[mt][nt][2];
                oc[CHS + 8] = d[mt][nt][3];
            }
        }
    }
}

// ---------------- launch ----------------
extern "C" void kernel_launch(void* const* d_in, const int* in_sizes, int n_in,
                              void* d_out, int out_size) {
    const float* xs[3];
    const float* w = nullptr;
    int nx = 0;
    for (int i = 0; i < n_in; ++i) {
        if (in_sizes[i] == C_N * 288) w = (const float*)d_in[i];
        else if (nx < 3) xs[nx++] = (const float*)d_in[i];
    }
    float* out = (float*)d_out;

    cudaFuncSetAttribute(fused_mma_kernel,
                         cudaFuncAttributeMaxDynamicSharedMemorySize, SMEM_SZ);

    prep_w_kernel<<<(KSTEPS * 6 * 32 + 255) / 256, 256>>>(w);
    fused_mma_kernel<<<B_N * 128 * 8, NTH, SMEM_SZ>>>(xs[0], xs[1], xs[2], out);
}